// round 1
// baseline (speedup 1.0000x reference)
#include <cuda_runtime.h>

#define FULLMASK 0xffffffffu

static constexpr int EMB = 32;
static constexpr int F   = 128;
static constexpr int NPG = 1024;            // nodes per graph
static constexpr int G   = 32;
static constexpr int NTOT = G * NPG;        // 32768

static constexpr size_t NE      = (size_t)G * NPG * NPG;   // 33,554,432 edges
static constexpr size_t OFF_XE  = 0;
static constexpr size_t OFF_SRC = (size_t)NTOT * EMB;      // 1,048,576
static constexpr size_t OFF_DST = OFF_SRC + NE;
static constexpr size_t OFF_W   = OFF_DST + NE;            // total 101,711,872

__device__ float g_centroid[EMB];
__device__ float g_scale;

// ---------------------------------------------------------------------------
// K1: xe = x @ W.  Warp-per-row, W in smem, x row in regs + shfl broadcast.
// grid 256 blocks x 256 threads; each warp does 16 rows.
// ---------------------------------------------------------------------------
__global__ __launch_bounds__(256) void k_xe(const float* __restrict__ x,
                                            const float* __restrict__ W,
                                            float* __restrict__ out) {
    __shared__ float sW[F * EMB];           // 16 KB
    const int t = threadIdx.x;
    for (int i = t; i < F * EMB; i += 256) sW[i] = W[i];
    __syncthreads();

    const int warp = t >> 5, lane = t & 31;
    const int rowBase = blockIdx.x * 128 + warp * 16;

    for (int r = 0; r < 16; r++) {
        const int row = rowBase + r;
        const float* xr = x + (size_t)row * F;
        float xv[4];
#pragma unroll
        for (int q = 0; q < 4; q++) xv[q] = xr[lane + 32 * q];
        float acc = 0.f;
#pragma unroll
        for (int k = 0; k < F; k++) {
            const float xb = __shfl_sync(FULLMASK, xv[k >> 5], k & 31);
            acc = fmaf(xb, sW[k * EMB + lane], acc);
        }
        out[OFF_XE + (size_t)row * EMB + lane] = acc;
    }
}

// ---------------------------------------------------------------------------
// K2: centroid = mean(xe[:1024], axis=0); scale = 0.9 / max|xe[:1024]-centroid|
// single block of 1024 threads.
// ---------------------------------------------------------------------------
__global__ __launch_bounds__(1024) void k_stats(const float* __restrict__ xe) {
    __shared__ float cshared[EMB];
    __shared__ float mred[32];
    const int t = threadIdx.x;
    const int lane = t & 31, warp = t >> 5;   // 32 warps, warp w owns dim w

    // column sum: warp w sums xe[r][w] over r = lane, lane+32, ...
    float s = 0.f;
    for (int r = lane; r < NPG; r += 32) s += xe[(size_t)r * EMB + warp];
#pragma unroll
    for (int o = 16; o > 0; o >>= 1) s += __shfl_down_sync(FULLMASK, s, o);
    if (lane == 0) cshared[warp] = s * (1.0f / (float)NPG);
    __syncthreads();
    if (t < EMB) g_centroid[t] = cshared[t];

    // max |x0 - centroid|
    float m = 0.f;
    for (int i = t; i < NPG * EMB; i += 1024)
        m = fmaxf(m, fabsf(xe[i] - cshared[i & 31]));
#pragma unroll
    for (int o = 16; o > 0; o >>= 1) m = fmaxf(m, __shfl_down_sync(FULLMASK, m, o));
    if (lane == 0) mred[warp] = m;
    __syncthreads();
    if (t < 32) {
        m = mred[t];
#pragma unroll
        for (int o = 16; o > 0; o >>= 1) m = fmaxf(m, __shfl_down_sync(FULLMASK, m, o));
        if (t == 0) g_scale = 0.9f / m;
    }
}

// ---------------------------------------------------------------------------
// K3: per graph g, 64x64 tile of A = sigmoid(T*(|thr| - max(||xi-xj||^2, 0)))
// plus fused src/dst index streams.  grid (16,16,32), 256 threads,
// 4x4 register micro-tile per thread, transposed smem tiles for LDS.128.
// ---------------------------------------------------------------------------
__global__ __launch_bounds__(256) void k_adj(const float* __restrict__ xe,
                                             const float* __restrict__ temp,
                                             const float* __restrict__ thr,
                                             float* __restrict__ out) {
    __shared__ float xiT[EMB][68];
    __shared__ float xjT[EMB][68];
    __shared__ float sqi[64], sqj[64];
    __shared__ float cent[EMB];

    const int g  = blockIdx.z;
    const int i0 = blockIdx.y * 64;
    const int j0 = blockIdx.x * 64;
    const int t  = threadIdx.x;

    if (t < EMB) cent[t] = g_centroid[t];
    const float scale = g_scale;
    __syncthreads();

    const float* base = xe + (size_t)g * NPG * EMB;

    // load + normalize tiles (coalesced global reads, transposed smem writes)
    for (int e = t; e < 64 * EMB; e += 256) {
        const int d = e & 31;
        const int r = e >> 5;
        xiT[d][r] = (base[(size_t)(i0 + r) * EMB + d] - cent[d]) * scale;
        xjT[d][r] = (base[(size_t)(j0 + r) * EMB + d] - cent[d]) * scale;
    }
    __syncthreads();

    if (t < 64) {
        float s = 0.f;
#pragma unroll
        for (int d = 0; d < EMB; d++) { const float v = xiT[d][t]; s = fmaf(v, v, s); }
        sqi[t] = s;
    } else if (t < 128) {
        const int r = t - 64;
        float s = 0.f;
#pragma unroll
        for (int d = 0; d < EMB; d++) { const float v = xjT[d][r]; s = fmaf(v, v, s); }
        sqj[r] = s;
    }
    __syncthreads();

    const int tx = t & 15, ty = t >> 4;
    const int ib = ty * 4, jb = tx * 4;

    float acc[4][4];
#pragma unroll
    for (int a = 0; a < 4; a++)
#pragma unroll
        for (int b = 0; b < 4; b++) acc[a][b] = 0.f;

#pragma unroll
    for (int d = 0; d < EMB; d++) {
        const float4 a = *(const float4*)&xiT[d][ib];
        const float4 b = *(const float4*)&xjT[d][jb];
        acc[0][0] = fmaf(a.x, b.x, acc[0][0]); acc[0][1] = fmaf(a.x, b.y, acc[0][1]);
        acc[0][2] = fmaf(a.x, b.z, acc[0][2]); acc[0][3] = fmaf(a.x, b.w, acc[0][3]);
        acc[1][0] = fmaf(a.y, b.x, acc[1][0]); acc[1][1] = fmaf(a.y, b.y, acc[1][1]);
        acc[1][2] = fmaf(a.y, b.z, acc[1][2]); acc[1][3] = fmaf(a.y, b.w, acc[1][3]);
        acc[2][0] = fmaf(a.z, b.x, acc[2][0]); acc[2][1] = fmaf(a.z, b.y, acc[2][1]);
        acc[2][2] = fmaf(a.z, b.z, acc[2][2]); acc[2][3] = fmaf(a.z, b.w, acc[2][3]);
        acc[3][0] = fmaf(a.w, b.x, acc[3][0]); acc[3][1] = fmaf(a.w, b.y, acc[3][1]);
        acc[3][2] = fmaf(a.w, b.z, acc[3][2]); acc[3][3] = fmaf(a.w, b.w, acc[3][3]);
    }

    const float T  = __ldg(temp);
    const float TH = fabsf(__ldg(thr));

    float* wout = out + OFF_W   + (size_t)g * NPG * NPG;
    float* sout = out + OFF_SRC + (size_t)g * NPG * NPG;
    float* dout = out + OFF_DST + (size_t)g * NPG * NPG;
    const int nodeBase = g * NPG;
    const float jf0 = (float)(nodeBase + j0 + jb);
    const float4 dv = make_float4(jf0, jf0 + 1.f, jf0 + 2.f, jf0 + 3.f);

#pragma unroll
    for (int ii = 0; ii < 4; ii++) {
        const int i = i0 + ib + ii;
        const float si = sqi[ib + ii];
        const float srcv = (float)(nodeBase + i);
        const float4 sv = make_float4(srcv, srcv, srcv, srcv);
        float4 wv;
        {
            float D;
            D = fmaxf(si + sqj[jb + 0] - 2.f * acc[ii][0], 0.f);
            wv.x = 1.f / (1.f + __expf(-(T * (TH - D))));
            D = fmaxf(si + sqj[jb + 1] - 2.f * acc[ii][1], 0.f);
            wv.y = 1.f / (1.f + __expf(-(T * (TH - D))));
            D = fmaxf(si + sqj[jb + 2] - 2.f * acc[ii][2], 0.f);
            wv.z = 1.f / (1.f + __expf(-(T * (TH - D))));
            D = fmaxf(si + sqj[jb + 3] - 2.f * acc[ii][3], 0.f);
            wv.w = 1.f / (1.f + __expf(-(T * (TH - D))));
        }
        const size_t row = (size_t)i * NPG + (j0 + jb);
        *(float4*)(wout + row) = wv;
        *(float4*)(sout + row) = sv;
        *(float4*)(dout + row) = dv;
    }
}

// ---------------------------------------------------------------------------
// launch
// inputs: 0=x [32768,128] f32, 1=W [128,32] f32, 2=temperature f32[1],
//         3=threshold f32[1], 4=batch (unused), 5=edge_index (unused),
//         6=num_graphs (unused, fixed 32)
// output (f32, concatenated): xe | src | dst | edge_weight
// ---------------------------------------------------------------------------
extern "C" void kernel_launch(void* const* d_in, const int* in_sizes, int n_in,
                              void* d_out, int out_size) {
    const float* x    = (const float*)d_in[0];
    const float* W    = (const float*)d_in[1];
    const float* temp = (const float*)d_in[2];
    const float* thr  = (const float*)d_in[3];
    float* out = (float*)d_out;

    k_xe<<<256, 256>>>(x, W, out);
    k_stats<<<1, 1024>>>(out + OFF_XE);
    dim3 grid(16, 16, 32);
    k_adj<<<grid, 256>>>(out + OFF_XE, temp, thr, out);
}

// round 2
// speedup vs baseline: 1.5854x; 1.5854x over previous
#include <cuda_runtime.h>

#define FULLMASK 0xffffffffu

static constexpr int EMB = 32;
static constexpr int F   = 128;
static constexpr int NPG = 1024;            // nodes per graph
static constexpr int G   = 32;
static constexpr int NTOT = G * NPG;        // 32768

static constexpr size_t NE      = (size_t)G * NPG * NPG;   // 33,554,432 edges
static constexpr size_t OFF_XE  = 0;
static constexpr size_t OFF_SRC = (size_t)NTOT * EMB;      // 1,048,576
static constexpr size_t OFF_DST = OFF_SRC + NE;
static constexpr size_t OFF_W   = OFF_DST + NE;

__device__ float g_sq[NTOT];     // per-node ||xe||^2 (raw)
__device__ float g_scale;        // 0.9 / max|x0 - centroid|
__device__ int   g_ctr = 0;

// ---------------------------------------------------------------------------
// K1: xe = x @ W  (+ per-row squared norms, + fused stats in last-done block)
// 1024 blocks x 256 threads; block handles 32 rows.
// Thread (r = t>>3, cg = t&7) computes 4 output cols via float4 ops.
// ---------------------------------------------------------------------------
__global__ __launch_bounds__(256) void k_xe(const float* __restrict__ x,
                                            const float* __restrict__ W,
                                            float* __restrict__ out) {
    __shared__ float sx[32 * 132];          // x tile, stride 132 (conflict-free)
    __shared__ float sW[F * EMB];           // 16 KB, [k][c]
    __shared__ float cpart[8][32];
    __shared__ float cent[32];
    __shared__ float mred[8];
    __shared__ int   isLast;

    const int t = threadIdx.x;
    const int row0 = blockIdx.x * 32;

    // load W (coalesced float4)
#pragma unroll
    for (int i = 0; i < 4; i++)
        ((float4*)sW)[t + 256 * i] = ((const float4*)W)[t + 256 * i];

    // stage x tile: 32 rows x 128 floats = 1024 float4
#pragma unroll
    for (int i = 0; i < 4; i++) {
        const int f = t + 256 * i;
        const int r = f >> 5, c4 = f & 31;
        const float4 v = ((const float4*)(x + (size_t)(row0 + r) * F))[c4];
        *(float4*)&sx[r * 132 + c4 * 4] = v;
    }
    __syncthreads();

    const int r = t >> 3, cg = t & 7;
    float a0 = 0.f, a1 = 0.f, a2 = 0.f, a3 = 0.f;
    const float* xr = &sx[r * 132];
#pragma unroll 8
    for (int k4 = 0; k4 < 32; k4++) {
        const float4 xq = *(const float4*)(xr + 4 * k4);
        float4 w;
        w = *(const float4*)&sW[(4 * k4 + 0) * EMB + 4 * cg];
        a0 = fmaf(xq.x, w.x, a0); a1 = fmaf(xq.x, w.y, a1);
        a2 = fmaf(xq.x, w.z, a2); a3 = fmaf(xq.x, w.w, a3);
        w = *(const float4*)&sW[(4 * k4 + 1) * EMB + 4 * cg];
        a0 = fmaf(xq.y, w.x, a0); a1 = fmaf(xq.y, w.y, a1);
        a2 = fmaf(xq.y, w.z, a2); a3 = fmaf(xq.y, w.w, a3);
        w = *(const float4*)&sW[(4 * k4 + 2) * EMB + 4 * cg];
        a0 = fmaf(xq.z, w.x, a0); a1 = fmaf(xq.z, w.y, a1);
        a2 = fmaf(xq.z, w.z, a2); a3 = fmaf(xq.z, w.w, a3);
        w = *(const float4*)&sW[(4 * k4 + 3) * EMB + 4 * cg];
        a0 = fmaf(xq.w, w.x, a0); a1 = fmaf(xq.w, w.y, a1);
        a2 = fmaf(xq.w, w.z, a2); a3 = fmaf(xq.w, w.w, a3);
    }
    const int row = row0 + r;
    ((float4*)(out + OFF_XE + (size_t)row * EMB))[cg] =
        make_float4(a0, a1, a2, a3);

    // per-row squared norm: butterfly over the 8 threads sharing a row
    float ps = a0 * a0 + a1 * a1 + a2 * a2 + a3 * a3;
    ps += __shfl_xor_sync(FULLMASK, ps, 1);
    ps += __shfl_xor_sync(FULLMASK, ps, 2);
    ps += __shfl_xor_sync(FULLMASK, ps, 4);
    if (cg == 0) g_sq[row] = ps;

    // ---- last-done block computes the scale (threadFenceReduction pattern)
    __threadfence();
    __syncthreads();
    if (t == 0) isLast = (atomicAdd(&g_ctr, 1) == (int)gridDim.x - 1);
    __syncthreads();
    if (!isLast) return;
    __threadfence();

    // centroid over xe[:1024]
    const int c = t & 31, rg = t >> 5;          // 8 row-groups x 32 cols
    float s = 0.f;
    for (int rr = rg * 128; rr < rg * 128 + 128; rr++)
        s += __ldcg(&out[OFF_XE + (size_t)rr * EMB + c]);
    cpart[rg][c] = s;
    __syncthreads();
    if (t < 32) {
        float cs = 0.f;
#pragma unroll
        for (int q = 0; q < 8; q++) cs += cpart[q][t];
        cent[t] = cs * (1.0f / (float)NPG);
    }
    __syncthreads();

    // max |x0 - centroid|
    float m = 0.f;
#pragma unroll 4
    for (int i = 0; i < 128; i++) {
        const int idx = t + 256 * i;
        m = fmaxf(m, fabsf(__ldcg(&out[OFF_XE + idx]) - cent[idx & 31]));
    }
#pragma unroll
    for (int o = 16; o > 0; o >>= 1)
        m = fmaxf(m, __shfl_xor_sync(FULLMASK, m, o));
    if ((t & 31) == 0) mred[t >> 5] = m;
    __syncthreads();
    if (t == 0) {
        float mm = mred[0];
#pragma unroll
        for (int q = 1; q < 8; q++) mm = fmaxf(mm, mred[q]);
        g_scale = 0.9f / mm;
        g_ctr = 0;                               // reset for next graph replay
    }
}

// ---------------------------------------------------------------------------
// K2: per graph g, 128x64 tile. D = s^2 * max(sq_i + sq_j - 2<xe_i,xe_j>, 0)
// on RAW xe (centroid cancels). w = 1/(1+exp(T*s^2*q - T*TH)).
// grid (16 j, 8 i, 32 g), 256 threads, 8x4 register micro-tile.
// ---------------------------------------------------------------------------
__global__ __launch_bounds__(256, 3) void k_adj(const float* __restrict__ xe,
                                                const float* __restrict__ temp,
                                                const float* __restrict__ thr,
                                                float* __restrict__ out) {
    __shared__ float xiT[EMB * 132];   // [d][r<128], stride 132
    __shared__ float xjT[EMB * 68];    // [d][r<64],  stride 68
    __shared__ float sqi[128], sqj[64];

    const int g  = blockIdx.z;
    const int i0 = blockIdx.y * 128;
    const int j0 = blockIdx.x * 64;
    const int t  = threadIdx.x;

    const float* base = xe + (size_t)g * NPG * EMB;

    // load xi tile (128 rows): coalesced float4, transposed scatter to smem
#pragma unroll
    for (int i = 0; i < 4; i++) {
        const int f = t + 256 * i;
        const int c = f & 7, rr = f >> 3;
        const float4 v = ((const float4*)(base + (size_t)(i0 + rr) * EMB))[c];
        xiT[(4 * c + 0) * 132 + rr] = v.x;
        xiT[(4 * c + 1) * 132 + rr] = v.y;
        xiT[(4 * c + 2) * 132 + rr] = v.z;
        xiT[(4 * c + 3) * 132 + rr] = v.w;
    }
    // load xj tile (64 rows)
#pragma unroll
    for (int i = 0; i < 2; i++) {
        const int f = t + 256 * i;
        const int c = f & 7, rr = f >> 3;
        const float4 v = ((const float4*)(base + (size_t)(j0 + rr) * EMB))[c];
        xjT[(4 * c + 0) * 68 + rr] = v.x;
        xjT[(4 * c + 1) * 68 + rr] = v.y;
        xjT[(4 * c + 2) * 68 + rr] = v.z;
        xjT[(4 * c + 3) * 68 + rr] = v.w;
    }
    if (t < 128)      sqi[t]       = g_sq[g * NPG + i0 + t];
    else if (t < 192) sqj[t - 128] = g_sq[g * NPG + j0 + (t - 128)];
    __syncthreads();

    const int tx = t & 15, ty = t >> 4;
    const int ib = 8 * ty, jb = 4 * tx;

    float acc[8][4];
#pragma unroll
    for (int a = 0; a < 8; a++)
#pragma unroll
        for (int b = 0; b < 4; b++) acc[a][b] = 0.f;

#pragma unroll 8
    for (int d = 0; d < EMB; d++) {
        const float4 p0 = *(const float4*)&xiT[d * 132 + ib];
        const float4 p1 = *(const float4*)&xiT[d * 132 + ib + 4];
        const float4 q  = *(const float4*)&xjT[d * 68 + jb];
        const float av[8] = {p0.x, p0.y, p0.z, p0.w, p1.x, p1.y, p1.z, p1.w};
#pragma unroll
        for (int a = 0; a < 8; a++) {
            acc[a][0] = fmaf(av[a], q.x, acc[a][0]);
            acc[a][1] = fmaf(av[a], q.y, acc[a][1]);
            acc[a][2] = fmaf(av[a], q.z, acc[a][2]);
            acc[a][3] = fmaf(av[a], q.w, acc[a][3]);
        }
    }

    const float T   = __ldg(temp);
    const float TH  = fabsf(__ldg(thr));
    const float s   = g_scale;
    const float Ts2 = T * s * s;
    const float nTT = -(T * TH);

    float* wout = out + OFF_W   + (size_t)g * NPG * NPG;
    float* sout = out + OFF_SRC + (size_t)g * NPG * NPG;
    float* dout = out + OFF_DST + (size_t)g * NPG * NPG;
    const int nodeBase = g * NPG;

    const float4 sj = *(const float4*)&sqj[jb];
    const float jf0 = (float)(nodeBase + j0 + jb);
    const float4 dv = make_float4(jf0, jf0 + 1.f, jf0 + 2.f, jf0 + 3.f);

#pragma unroll
    for (int ii = 0; ii < 8; ii++) {
        const int i = i0 + ib + ii;
        const float si = sqi[ib + ii];
        float4 wv;
        {
            float qv, e;
            qv = fmaxf(fmaf(-2.f, acc[ii][0], si + sj.x), 0.f);
            e  = __expf(fmaf(Ts2, qv, nTT));
            wv.x = __fdividef(1.f, 1.f + e);
            qv = fmaxf(fmaf(-2.f, acc[ii][1], si + sj.y), 0.f);
            e  = __expf(fmaf(Ts2, qv, nTT));
            wv.y = __fdividef(1.f, 1.f + e);
            qv = fmaxf(fmaf(-2.f, acc[ii][2], si + sj.z), 0.f);
            e  = __expf(fmaf(Ts2, qv, nTT));
            wv.z = __fdividef(1.f, 1.f + e);
            qv = fmaxf(fmaf(-2.f, acc[ii][3], si + sj.w), 0.f);
            e  = __expf(fmaf(Ts2, qv, nTT));
            wv.w = __fdividef(1.f, 1.f + e);
        }
        const float srcf = (float)(nodeBase + i);
        const float4 sv  = make_float4(srcf, srcf, srcf, srcf);
        const size_t off = (size_t)i * NPG + (j0 + jb);
        __stcs((float4*)(wout + off), wv);
        __stcs((float4*)(sout + off), sv);
        __stcs((float4*)(dout + off), dv);
    }
}

// ---------------------------------------------------------------------------
// inputs: 0=x [32768,128] f32, 1=W [128,32] f32, 2=temperature, 3=threshold,
//         4=batch (unused), 5=edge_index (unused), 6=num_graphs (unused)
// output (f32): xe | src | dst | edge_weight
// ---------------------------------------------------------------------------
extern "C" void kernel_launch(void* const* d_in, const int* in_sizes, int n_in,
                              void* d_out, int out_size) {
    const float* x    = (const float*)d_in[0];
    const float* W    = (const float*)d_in[1];
    const float* temp = (const float*)d_in[2];
    const float* thr  = (const float*)d_in[3];
    float* out = (float*)d_out;

    k_xe<<<NTOT / 32, 256>>>(x, W, out);
    dim3 grid(16, 8, G);
    k_adj<<<grid, 256>>>(out + OFF_XE, temp, thr, out);
}